// round 8
// baseline (speedup 1.0000x reference)
#include <cuda_runtime.h>
#include <cstdint>

#define SORB  64
#define HID   256
#define BATCH 8192
#define LEN   1056
#define NSTEP 32
#define TB    4      // batch elements per warp

// Packed transposed tables (zero for j >= 2m):
//   g_ut[j][m]  = pack( -Σ_h W[h,start+j]·w0 , -Σ_h W[h,start+j]·w1 )   (low, high)
//   g_base[m]   = pack( -Σhb·w0 - 0.5Σw0² , -Σhb·w1 - 0.5Σw1² )
//   g_negQ01[m] = -Σw0·w1
__device__ unsigned long long g_ut[64][32];
__device__ unsigned long long g_base[32];
__device__ float              g_negQ01[32];

__device__ __forceinline__ unsigned long long packf2(float a, float b) {
    return (unsigned long long)__float_as_uint(a)
         | ((unsigned long long)__float_as_uint(b) << 32);
}

__global__ __launch_bounds__(512)
void precompute_kernel(const float* __restrict__ W, const float* __restrict__ hb)
{
    const int m = blockIdx.x;
    const int k = 2 * m, start = m * (m + 1);
    __shared__ float sw0[HID], sw1[HID];
    __shared__ float p0[8][64], p1[8][64];
    __shared__ float cst[5];
    const int tid = threadIdx.x;
    const int lane = tid & 31, wid = tid >> 5;

    if (tid < HID) {                       // stage w0,w1 (strided gather, once)
        const float* p = W + (size_t)tid * LEN + start + k;
        sw0[tid] = p[0];
        sw1[tid] = p[1];
    }
    __syncthreads();

    // u-partials: 8 h-groups of 32, coalesced over j
    {
        const int j = tid & 63, grp = tid >> 6;
        float a0 = 0.f, a1 = 0.f;
        if (j < k) {
            const float* pw = W + start + j + (size_t)grp * 32 * LEN;
            const float* s0 = sw0 + grp * 32;
            const float* s1 = sw1 + grp * 32;
            #pragma unroll
            for (int h = 0; h < 32; ++h) {
                const float wv = pw[(size_t)h * LEN];
                a0 = fmaf(wv, s0[h], a0);
                a1 = fmaf(wv, s1[h], a1);
            }
        }
        p0[grp][j] = a0;
        p1[grp][j] = a1;
    }
    // constants in warps 8..12 (independent of p-arrays)
    if (wid >= 8 && wid <= 12) {
        const int which = wid - 8;
        float acc = 0.f;
        #pragma unroll
        for (int hh = lane; hh < HID; hh += 32) {
            float a, b;
            if      (which == 0) { a = hb[hh];  b = sw0[hh]; }
            else if (which == 1) { a = hb[hh];  b = sw1[hh]; }
            else if (which == 2) { a = sw0[hh]; b = sw0[hh]; }
            else if (which == 3) { a = sw1[hh]; b = sw1[hh]; }
            else                 { a = sw0[hh]; b = sw1[hh]; }
            acc = fmaf(a, b, acc);
        }
        acc += __shfl_xor_sync(0xffffffffu, acc, 16);
        acc += __shfl_xor_sync(0xffffffffu, acc, 8);
        acc += __shfl_xor_sync(0xffffffffu, acc, 4);
        acc += __shfl_xor_sync(0xffffffffu, acc, 2);
        acc += __shfl_xor_sync(0xffffffffu, acc, 1);
        if (lane == 0) cst[which] = acc;
    }
    __syncthreads();

    if (tid < 64) {
        float s0 = 0.f, s1 = 0.f;
        #pragma unroll
        for (int g = 0; g < 8; ++g) { s0 += p0[g][tid]; s1 += p1[g][tid]; }
        g_ut[tid][m] = packf2(-s0, -s1);
    } else if (tid == 64) {
        g_base[m]   = packf2(-cst[0] - 0.5f * cst[2], -cst[1] - 0.5f * cst[3]);
        g_negQ01[m] = -cst[4];
    }
}

// exp(L) for |L| <= 0.05, rel err < 5e-8
__device__ __forceinline__ float expq(float L) {
    return fmaf(L, fmaf(L, fmaf(L, 0.16666667f, 0.5f), 1.0f), 1.0f);
}

// Predicated packed accumulate: if (bit) L12 += uv  (two f32 lanes at once)
__device__ __forceinline__ void acc_f32x2(unsigned long long& L12,
                                          unsigned bit, unsigned long long uv) {
    asm("{\n\t"
        ".reg .pred p;\n\t"
        "setp.ne.b32 p, %1, 0;\n\t"
        "@p add.rn.f32x2 %0, %0, %2;\n\t"
        "}" : "+l"(L12) : "r"(bit), "l"(uv));
}

// 2 warps/block, TB batch elements per warp; lane = step m. No smem, tables via L1.
__global__ __launch_bounds__(64)
void rbm_main_kernel(const int* __restrict__ x, float* __restrict__ out)
{
    const int tid  = threadIdx.x;
    const int lane = tid & 31, wid = tid >> 5;
    const int m    = lane;
    const int k    = 2 * m;

    // This warp's TB batch elements: pack bits (warp-uniform words)
    const int b0 = (blockIdx.x * 2 + wid) * TB;
    unsigned lo[TB], hi[TB];
    #pragma unroll
    for (int t = 0; t < TB; ++t) {
        const int v0 = x[(size_t)(b0 + t) * SORB + lane];
        const int v1 = x[(size_t)(b0 + t) * SORB + 32 + lane];
        lo[t] = __ballot_sync(0xffffffffu, v0 > 0);
        hi[t] = __ballot_sync(0xffffffffu, v1 > 0);
    }

    // Packed {L1, L2} accumulators
    unsigned long long L12[TB];
    {
        const unsigned long long base = __ldg(&g_base[m]);
        #pragma unroll
        for (int t = 0; t < TB; ++t) L12[t] = base;
    }

    // Dense accumulation: 64 coalesced L1-resident loads serve TB elements.
    #pragma unroll
    for (int j = 0; j < 32; ++j) {
        const unsigned long long uv = __ldg(&g_ut[j][m]);
        #pragma unroll
        for (int t = 0; t < TB; ++t)
            acc_f32x2(L12[t], lo[t] & (1u << j), uv);
    }
    #pragma unroll
    for (int j = 0; j < 32; ++j) {
        const unsigned long long uv = __ldg(&g_ut[j + 32][m]);
        #pragma unroll
        for (int t = 0; t < TB; ++t)
            acc_f32x2(L12[t], hi[t] & (1u << j), uv);
    }

    // masks for popcounts below position k (lane-dependent, batch-independent)
    const unsigned mlo = (k >= 32) ? 0xffffffffu : ((1u << k) - 1u);
    const unsigned mhi = (k > 32) ? ((1u << (k - 32)) - 1u) : 0u;
    const float negQ01 = __ldg(&g_negQ01[m]);

    float terms[TB];
    #pragma unroll
    for (int t = 0; t < TB; ++t) {
        const float L1 = __uint_as_float((unsigned)(L12[t] & 0xffffffffu));
        const float L2 = __uint_as_float((unsigned)(L12[t] >> 32));
        const float L3 = L1 + L2 + negQ01;
        float v0f = 1.f, v1f = expq(L1), v2f = expq(L2), v3f = expq(L3);

        const int nu = __popc(lo[t] & 0x55555555u & mlo) + __popc(hi[t] & 0x55555555u & mhi);
        const int nd = __popc(lo[t] & 0xAAAAAAAAu & mlo) + __popc(hi[t] & 0xAAAAAAAAu & mhi);

        if (m >= 8) {                        // SYMMETRY && alpha_e <= k
            const int lower = m - 16;        // base + k/2
            const bool ou = nu < 16, uu = nu > lower;
            const bool od = nd < 16, ud = nd > lower;
            v0f = (uu && ud) ? v0f : 0.f;
            v1f = (ou && ud) ? v1f : 0.f;
            v2f = (uu && od) ? v2f : 0.f;
            v3f = (ou && od) ? v3f : 0.f;
        }

        const float n2 = v0f*v0f + v1f*v1f + v2f*v2f + v3f*v3f;
        float inv = rsqrtf(fmaxf(n2, 1e-24f));
        inv = inv * fmaf(-0.5f * n2 * inv, inv, 1.5f);   // Newton

        const int bu = (k < 32) ? ((lo[t] >> k) & 1)       : ((hi[t] >> (k - 32)) & 1);
        const int bd = (k < 32) ? ((lo[t] >> (k + 1)) & 1) : ((hi[t] >> (k - 31)) & 1);
        const int st = bu + 2 * bd;
        const float vs = st == 0 ? v0f : st == 1 ? v1f : st == 2 ? v2f : v3f;

        float term = vs * inv;
        term *= __shfl_xor_sync(0xffffffffu, term, 16);
        term *= __shfl_xor_sync(0xffffffffu, term, 8);
        term *= __shfl_xor_sync(0xffffffffu, term, 4);
        term *= __shfl_xor_sync(0xffffffffu, term, 2);
        term *= __shfl_xor_sync(0xffffffffu, term, 1);
        terms[t] = term;
    }

    // lanes 0..TB-1 write the TB results
    float o = terms[0];
    #pragma unroll
    for (int t = 1; t < TB; ++t) o = (lane == t) ? terms[t] : o;
    if (lane < TB) out[b0 + lane] = o;
}

extern "C" void kernel_launch(void* const* d_in, const int* in_sizes, int n_in,
                              void* d_out, int out_size)
{
    const int*   x   = (const int*)d_in[0];
    const float* W   = (const float*)d_in[1];
    const float* hb  = (const float*)d_in[2];
    float*       out = (float*)d_out;

    precompute_kernel<<<NSTEP, 512>>>(W, hb);
    rbm_main_kernel<<<BATCH / (2 * TB), 64>>>(x, out);
}

// round 9
// speedup vs baseline: 1.0890x; 1.0890x over previous
#include <cuda_runtime.h>
#include <cstdint>

#define SORB  64
#define HID   256
#define BATCH 8192
#define LEN   1056
#define NSTEP 32
#define TB    2      // batch elements per warp

// Transposed, NEGATED per-step tables (zero for j >= 2m):
//   g_ut[j][m] = ( -Σ_h W[h,start+j]·w0, -Σ_h W[h,start+j]·w1 )
//   g_cstT[0][m] = -Σhb·w0 - 0.5Σw0²   (L1 base)
//   g_cstT[1][m] = -Σhb·w1 - 0.5Σw1²   (L2 base)
//   g_cstT[2][m] = -Σw0·w1             (L3 = L1+L2+this)
__device__ float2 g_ut[64][32];
__device__ float  g_cstT[4][32];

__global__ __launch_bounds__(512)
void precompute_kernel(const float* __restrict__ W, const float* __restrict__ hb)
{
    const int m = blockIdx.x;
    const int k = 2 * m, start = m * (m + 1);
    __shared__ float sw0[HID], sw1[HID];
    __shared__ float p0[8][64], p1[8][64];
    __shared__ float cst[5];
    const int tid = threadIdx.x;
    const int lane = tid & 31, wid = tid >> 5;

    if (tid < HID) {                       // stage w0,w1 (strided gather, once)
        const float* p = W + (size_t)tid * LEN + start + k;
        sw0[tid] = p[0];
        sw1[tid] = p[1];
    }
    __syncthreads();

    // u-partials: 8 h-groups of 32, coalesced over j
    {
        const int j = tid & 63, grp = tid >> 6;
        float a0 = 0.f, a1 = 0.f;
        if (j < k) {
            const float* pw = W + start + j + (size_t)grp * 32 * LEN;
            const float* s0 = sw0 + grp * 32;
            const float* s1 = sw1 + grp * 32;
            #pragma unroll
            for (int h = 0; h < 32; ++h) {
                const float wv = pw[(size_t)h * LEN];
                a0 = fmaf(wv, s0[h], a0);
                a1 = fmaf(wv, s1[h], a1);
            }
        }
        p0[grp][j] = a0;
        p1[grp][j] = a1;
    }
    // constants in warps 8..12 (independent of p-arrays)
    if (wid >= 8 && wid <= 12) {
        const int which = wid - 8;
        float acc = 0.f;
        #pragma unroll
        for (int hh = lane; hh < HID; hh += 32) {
            float a, b;
            if      (which == 0) { a = hb[hh];  b = sw0[hh]; }
            else if (which == 1) { a = hb[hh];  b = sw1[hh]; }
            else if (which == 2) { a = sw0[hh]; b = sw0[hh]; }
            else if (which == 3) { a = sw1[hh]; b = sw1[hh]; }
            else                 { a = sw0[hh]; b = sw1[hh]; }
            acc = fmaf(a, b, acc);
        }
        acc += __shfl_xor_sync(0xffffffffu, acc, 16);
        acc += __shfl_xor_sync(0xffffffffu, acc, 8);
        acc += __shfl_xor_sync(0xffffffffu, acc, 4);
        acc += __shfl_xor_sync(0xffffffffu, acc, 2);
        acc += __shfl_xor_sync(0xffffffffu, acc, 1);
        if (lane == 0) cst[which] = acc;
    }
    __syncthreads();

    if (tid < 64) {
        float s0 = 0.f, s1 = 0.f;
        #pragma unroll
        for (int g = 0; g < 8; ++g) { s0 += p0[g][tid]; s1 += p1[g][tid]; }
        g_ut[tid][m] = make_float2(-s0, -s1);
    } else if (tid == 64) {
        g_cstT[0][m] = -cst[0] - 0.5f * cst[2];
        g_cstT[1][m] = -cst[1] - 0.5f * cst[3];
        g_cstT[2][m] = -cst[4];
    }
}

// exp(L) for |L| <= 0.05, rel err < 5e-8
__device__ __forceinline__ float expq(float L) {
    return fmaf(L, fmaf(L, fmaf(L, 0.16666667f, 0.5f), 1.0f), 1.0f);
}

// 4 warps/block, TB batch elements per warp; lane = step m. Branch-free mask-FMA.
__global__ __launch_bounds__(128)
void rbm_main_kernel(const int* __restrict__ x, float* __restrict__ out)
{
    __shared__ float2 sut[64][32];
    __shared__ float  sct[4][32];

    const int tid  = threadIdx.x;
    const int lane = tid & 31, wid = tid >> 5;

    // Stage tables (2048 float2 / 128 thr = 16 each)
    #pragma unroll
    for (int r = 0; r < 16; ++r)
        ((float2*)sut)[r * 128 + tid] = ((const float2*)g_ut)[r * 128 + tid];
    if (tid < 4 * 32)
        ((float*)sct)[tid] = ((const float*)g_cstT)[tid];

    // This warp's TB batch elements: pack bits (warp-uniform words)
    const int b0 = (blockIdx.x * 4 + wid) * TB;
    unsigned lo[TB], hi[TB];
    #pragma unroll
    for (int t = 0; t < TB; ++t) {
        const int v0 = x[(size_t)(b0 + t) * SORB + lane];
        const int v1 = x[(size_t)(b0 + t) * SORB + 32 + lane];
        lo[t] = __ballot_sync(0xffffffffu, v0 > 0);
        hi[t] = __ballot_sync(0xffffffffu, v1 > 0);
    }
    __syncthreads();

    const int m = lane;
    const int k = 2 * m;

    // Dense accumulation: 64 shared loads serve TB elements, no branches.
    float L1[TB], L2[TB];
    #pragma unroll
    for (int t = 0; t < TB; ++t) { L1[t] = sct[0][m]; L2[t] = sct[1][m]; }

    #pragma unroll
    for (int j = 0; j < 32; ++j) {
        const float2 uv = sut[j][m];
        #pragma unroll
        for (int t = 0; t < TB; ++t) {
            const float msk = __uint_as_float(((lo[t] >> j) & 1u) * 0x3f800000u);
            L1[t] = fmaf(msk, uv.x, L1[t]);
            L2[t] = fmaf(msk, uv.y, L2[t]);
        }
    }
    #pragma unroll
    for (int j = 0; j < 32; ++j) {
        const float2 uv = sut[j + 32][m];
        #pragma unroll
        for (int t = 0; t < TB; ++t) {
            const float msk = __uint_as_float(((hi[t] >> j) & 1u) * 0x3f800000u);
            L1[t] = fmaf(msk, uv.x, L1[t]);
            L2[t] = fmaf(msk, uv.y, L2[t]);
        }
    }

    // masks for popcounts below position k (lane-dependent, batch-independent)
    const unsigned mlo = (k >= 32) ? 0xffffffffu : ((1u << k) - 1u);
    const unsigned mhi = (k > 32) ? ((1u << (k - 32)) - 1u) : 0u;
    const float negQ01 = sct[2][m];

    float terms[TB];
    #pragma unroll
    for (int t = 0; t < TB; ++t) {
        const float L3 = L1[t] + L2[t] + negQ01;
        float v0f = 1.f, v1f = expq(L1[t]), v2f = expq(L2[t]), v3f = expq(L3);

        const int nu = __popc(lo[t] & 0x55555555u & mlo) + __popc(hi[t] & 0x55555555u & mhi);
        const int nd = __popc(lo[t] & 0xAAAAAAAAu & mlo) + __popc(hi[t] & 0xAAAAAAAAu & mhi);

        if (m >= 8) {                        // SYMMETRY && alpha_e <= k
            const int lower = m - 16;        // base + k/2
            const bool ou = nu < 16, uu = nu > lower;
            const bool od = nd < 16, ud = nd > lower;
            v0f = (uu && ud) ? v0f : 0.f;
            v1f = (ou && ud) ? v1f : 0.f;
            v2f = (uu && od) ? v2f : 0.f;
            v3f = (ou && od) ? v3f : 0.f;
        }

        const float n2 = v0f*v0f + v1f*v1f + v2f*v2f + v3f*v3f;
        float inv = rsqrtf(fmaxf(n2, 1e-24f));
        inv = inv * fmaf(-0.5f * n2 * inv, inv, 1.5f);   // Newton

        const int bu = (k < 32) ? ((lo[t] >> k) & 1)       : ((hi[t] >> (k - 32)) & 1);
        const int bd = (k < 32) ? ((lo[t] >> (k + 1)) & 1) : ((hi[t] >> (k - 31)) & 1);
        const int st = bu + 2 * bd;
        const float vs = st == 0 ? v0f : st == 1 ? v1f : st == 2 ? v2f : v3f;

        float term = vs * inv;
        term *= __shfl_xor_sync(0xffffffffu, term, 16);
        term *= __shfl_xor_sync(0xffffffffu, term, 8);
        term *= __shfl_xor_sync(0xffffffffu, term, 4);
        term *= __shfl_xor_sync(0xffffffffu, term, 2);
        term *= __shfl_xor_sync(0xffffffffu, term, 1);
        terms[t] = term;
    }

    // lanes 0..TB-1 write the TB results
    float o = terms[0];
    #pragma unroll
    for (int t = 1; t < TB; ++t) o = (lane == t) ? terms[t] : o;
    if (lane < TB) out[b0 + lane] = o;
}

extern "C" void kernel_launch(void* const* d_in, const int* in_sizes, int n_in,
                              void* d_out, int out_size)
{
    const int*   x   = (const int*)d_in[0];
    const float* W   = (const float*)d_in[1];
    const float* hb  = (const float*)d_in[2];
    float*       out = (float*)d_out;

    precompute_kernel<<<NSTEP, 512>>>(W, hb);
    rbm_main_kernel<<<BATCH / (4 * TB), 128>>>(x, out);
}

// round 10
// speedup vs baseline: 1.1499x; 1.0559x over previous
#include <cuda_runtime.h>
#include <cstdint>

#define SORB  64
#define HID   256
#define BATCH 8192
#define LEN   1056
#define NSTEP 32
#define TB    2      // batch elements per warp

// Nibble subset-sum table:
//   g_nib[p][nib][m] = ( -Σ_{b set in nib} Σ_h W[h,start(m)+4p+b]·w0^m ,  same w/ w1 )
//   (u[j]=0 for j >= 2m folds the step length in automatically)
// g_cstT[0][m] = -Σhb·w0 - 0.5Σw0² ; [1]: w1 version ; [2] = -Σw0·w1
__device__ float2 g_nib[16][16][32];
__device__ float  g_cstT[4][32];

__global__ __launch_bounds__(512)
void precompute_kernel(const float* __restrict__ W, const float* __restrict__ hb)
{
    const int m = blockIdx.x;
    const int k = 2 * m, start = m * (m + 1);
    __shared__ float  sw0[HID], sw1[HID];
    __shared__ float  p0[8][64], p1[8][64];
    __shared__ float2 su[64];
    __shared__ float  cst[5];
    const int tid = threadIdx.x;
    const int lane = tid & 31, wid = tid >> 5;

    if (tid < HID) {                       // stage w0,w1 (strided gather, once)
        const float* p = W + (size_t)tid * LEN + start + k;
        sw0[tid] = p[0];
        sw1[tid] = p[1];
    }
    __syncthreads();

    // u-partials: 8 h-groups of 32, coalesced over j
    {
        const int j = tid & 63, grp = tid >> 6;
        float a0 = 0.f, a1 = 0.f;
        if (j < k) {
            const float* pw = W + start + j + (size_t)grp * 32 * LEN;
            const float* s0 = sw0 + grp * 32;
            const float* s1 = sw1 + grp * 32;
            #pragma unroll
            for (int h = 0; h < 32; ++h) {
                const float wv = pw[(size_t)h * LEN];
                a0 = fmaf(wv, s0[h], a0);
                a1 = fmaf(wv, s1[h], a1);
            }
        }
        p0[grp][j] = a0;
        p1[grp][j] = a1;
    }
    // constants in warps 8..12 (independent of p-arrays)
    if (wid >= 8 && wid <= 12) {
        const int which = wid - 8;
        float acc = 0.f;
        #pragma unroll
        for (int hh = lane; hh < HID; hh += 32) {
            float a, b;
            if      (which == 0) { a = hb[hh];  b = sw0[hh]; }
            else if (which == 1) { a = hb[hh];  b = sw1[hh]; }
            else if (which == 2) { a = sw0[hh]; b = sw0[hh]; }
            else if (which == 3) { a = sw1[hh]; b = sw1[hh]; }
            else                 { a = sw0[hh]; b = sw1[hh]; }
            acc = fmaf(a, b, acc);
        }
        acc += __shfl_xor_sync(0xffffffffu, acc, 16);
        acc += __shfl_xor_sync(0xffffffffu, acc, 8);
        acc += __shfl_xor_sync(0xffffffffu, acc, 4);
        acc += __shfl_xor_sync(0xffffffffu, acc, 2);
        acc += __shfl_xor_sync(0xffffffffu, acc, 1);
        if (lane == 0) cst[which] = acc;
    }
    __syncthreads();

    if (tid < 64) {
        float s0 = 0.f, s1 = 0.f;
        #pragma unroll
        for (int g = 0; g < 8; ++g) { s0 += p0[g][tid]; s1 += p1[g][tid]; }
        su[tid] = make_float2(-s0, -s1);
    } else if (tid == 64) {
        g_cstT[0][m] = -cst[0] - 0.5f * cst[2];
        g_cstT[1][m] = -cst[1] - 0.5f * cst[3];
        g_cstT[2][m] = -cst[4];
    }
    __syncthreads();

    // Build nibble subset-sum table: tid 0..255 -> (pos, nib)
    if (tid < 256) {
        const int pos = tid >> 4, nib = tid & 15;
        float a0 = 0.f, a1 = 0.f;
        #pragma unroll
        for (int b = 0; b < 4; ++b) {
            if ((nib >> b) & 1) {
                const float2 u = su[pos * 4 + b];
                a0 += u.x; a1 += u.y;
            }
        }
        g_nib[pos][nib][m] = make_float2(a0, a1);
    }
}

// exp(L) for |L| <= 0.05, rel err < 5e-8
__device__ __forceinline__ float expq(float L) {
    return fmaf(L, fmaf(L, fmaf(L, 0.16666667f, 0.5f), 1.0f), 1.0f);
}

// 4 warps/block, TB batch elements per warp; lane = step m.
// No smem, no syncthreads: nibble table via L1-resident LDG.
__global__ __launch_bounds__(128)
void rbm_main_kernel(const int* __restrict__ x, float* __restrict__ out)
{
    const int tid  = threadIdx.x;
    const int lane = tid & 31, wid = tid >> 5;
    const int m    = lane;
    const int k    = 2 * m;

    // This warp's TB batch elements: pack bits (warp-uniform words)
    const int b0 = (blockIdx.x * 4 + wid) * TB;
    unsigned lo[TB], hi[TB];
    #pragma unroll
    for (int t = 0; t < TB; ++t) {
        const int v0 = x[(size_t)(b0 + t) * SORB + lane];
        const int v1 = x[(size_t)(b0 + t) * SORB + 32 + lane];
        lo[t] = __ballot_sync(0xffffffffu, v0 > 0);
        hi[t] = __ballot_sync(0xffffffffu, v1 > 0);
    }

    float L1[TB], L2[TB];
    #pragma unroll
    for (int t = 0; t < TB; ++t) {
        L1[t] = __ldg(&g_cstT[0][m]);
        L2[t] = __ldg(&g_cstT[1][m]);
    }

    // Per-lane base into the nibble table (float2 at [p][nib][lane])
    const char* base = (const char*)g_nib + (size_t)lane * sizeof(float2);

    // 16 nibble positions; each lookup covers 4 x-bits. nib*256 extracted as
    // a byte offset with one SHF + one LOP3.
    #pragma unroll
    for (int p = 0; p < 8; ++p) {
        #pragma unroll
        for (int t = 0; t < TB; ++t) {
            const unsigned off = (p < 2) ? ((lo[t] << (8 - 4 * p)) & 0xF00u)
                                         : ((lo[t] >> (4 * p - 8)) & 0xF00u);
            const float2 v = __ldg((const float2*)(base + (size_t)p * 4096 + off));
            L1[t] += v.x; L2[t] += v.y;
        }
    }
    #pragma unroll
    for (int p = 0; p < 8; ++p) {
        #pragma unroll
        for (int t = 0; t < TB; ++t) {
            const unsigned off = (p < 2) ? ((hi[t] << (8 - 4 * p)) & 0xF00u)
                                         : ((hi[t] >> (4 * p - 8)) & 0xF00u);
            const float2 v = __ldg((const float2*)(base + (size_t)(p + 8) * 4096 + off));
            L1[t] += v.x; L2[t] += v.y;
        }
    }

    // masks for popcounts below position k (lane-dependent, batch-independent)
    const unsigned mlo = (k >= 32) ? 0xffffffffu : ((1u << k) - 1u);
    const unsigned mhi = (k > 32) ? ((1u << (k - 32)) - 1u) : 0u;
    const float negQ01 = __ldg(&g_cstT[2][m]);

    float terms[TB];
    #pragma unroll
    for (int t = 0; t < TB; ++t) {
        const float L3 = L1[t] + L2[t] + negQ01;
        float v0f = 1.f, v1f = expq(L1[t]), v2f = expq(L2[t]), v3f = expq(L3);

        const int nu = __popc(lo[t] & 0x55555555u & mlo) + __popc(hi[t] & 0x55555555u & mhi);
        const int nd = __popc(lo[t] & 0xAAAAAAAAu & mlo) + __popc(hi[t] & 0xAAAAAAAAu & mhi);

        if (m >= 8) {                        // SYMMETRY && alpha_e <= k
            const int lower = m - 16;        // base + k/2
            const bool ou = nu < 16, uu = nu > lower;
            const bool od = nd < 16, ud = nd > lower;
            v0f = (uu && ud) ? v0f : 0.f;
            v1f = (ou && ud) ? v1f : 0.f;
            v2f = (uu && od) ? v2f : 0.f;
            v3f = (ou && od) ? v3f : 0.f;
        }

        const float n2 = v0f*v0f + v1f*v1f + v2f*v2f + v3f*v3f;
        float inv = rsqrtf(fmaxf(n2, 1e-24f));
        inv = inv * fmaf(-0.5f * n2 * inv, inv, 1.5f);   // Newton

        const int bu = (k < 32) ? ((lo[t] >> k) & 1)       : ((hi[t] >> (k - 32)) & 1);
        const int bd = (k < 32) ? ((lo[t] >> (k + 1)) & 1) : ((hi[t] >> (k - 31)) & 1);
        const int st = bu + 2 * bd;
        const float vs = st == 0 ? v0f : st == 1 ? v1f : st == 2 ? v2f : v3f;

        float term = vs * inv;
        term *= __shfl_xor_sync(0xffffffffu, term, 16);
        term *= __shfl_xor_sync(0xffffffffu, term, 8);
        term *= __shfl_xor_sync(0xffffffffu, term, 4);
        term *= __shfl_xor_sync(0xffffffffu, term, 2);
        term *= __shfl_xor_sync(0xffffffffu, term, 1);
        terms[t] = term;
    }

    // lanes 0..TB-1 write the TB results
    float o = terms[0];
    #pragma unroll
    for (int t = 1; t < TB; ++t) o = (lane == t) ? terms[t] : o;
    if (lane < TB) out[b0 + lane] = o;
}

extern "C" void kernel_launch(void* const* d_in, const int* in_sizes, int n_in,
                              void* d_out, int out_size)
{
    const int*   x   = (const int*)d_in[0];
    const float* W   = (const float*)d_in[1];
    const float* hb  = (const float*)d_in[2];
    float*       out = (float*)d_out;

    precompute_kernel<<<NSTEP, 512>>>(W, hb);
    rbm_main_kernel<<<BATCH / (4 * TB), 128>>>(x, out);
}

// round 11
// speedup vs baseline: 1.2660x; 1.1010x over previous
#include <cuda_runtime.h>
#include <cstdint>

#define SORB  64
#define HID   256
#define BATCH 8192
#define LEN   1056
#define NSTEP 32
#define TB    4      // batch elements per warp

// Nibble subset-sum table:
//   g_nib[p][nib][m] = -Σ_{b set in nib} Σ_h W[h,start(m)+4p+b]·(w0,w1)^m
//   (u[j]=0 for j >= 2m folds the step length in automatically)
// g_cstT[0][m] = -Σhb·w0 - 0.5Σw0² ; [1]: w1 version ; [2] = -Σw0·w1
__device__ float2 g_nib[16][16][32];
__device__ float  g_cstT[4][32];

// grid 128 = (m, quarter q): block handles j in [16q, 16q+16) and nibble
// positions 4q..4q+3 for step m.
__global__ __launch_bounds__(256)
void precompute_kernel(const float* __restrict__ W, const float* __restrict__ hb)
{
    const int m = blockIdx.x >> 2, q = blockIdx.x & 3;
    const int k = 2 * m, start = m * (m + 1);
    __shared__ float  sw0[HID], sw1[HID];
    __shared__ float  p0[16][16], p1[16][16];
    __shared__ float2 su[16];
    const int tid = threadIdx.x;
    const int lane = tid & 31, wid = tid >> 5;

    // stage w0,w1 (strided gather)
    {
        const float* p = W + (size_t)tid * LEN + start + k;
        sw0[tid] = p[0];
        sw1[tid] = p[1];
    }
    __syncthreads();

    // u-partials: 16 local j × 16 h-groups of 16
    {
        const int jl = tid & 15, grp = tid >> 4;
        const int j = q * 16 + jl;
        float a0 = 0.f, a1 = 0.f;
        if (j < k) {
            const float* pw = W + start + j + (size_t)grp * 16 * LEN;
            const float* s0 = sw0 + grp * 16;
            const float* s1 = sw1 + grp * 16;
            #pragma unroll
            for (int h = 0; h < 16; ++h) {
                const float wv = pw[(size_t)h * LEN];
                a0 = fmaf(wv, s0[h], a0);
                a1 = fmaf(wv, s1[h], a1);
            }
        }
        p0[jl][grp] = a0;
        p1[jl][grp] = a1;
    }
    __syncthreads();

    if (tid < 16) {
        float s0 = 0.f, s1 = 0.f;
        #pragma unroll
        for (int g = 0; g < 16; ++g) { s0 += p0[tid][g]; s1 += p1[tid][g]; }
        su[tid] = make_float2(-s0, -s1);
    } else if (q == 0 && wid >= 2 && wid <= 6) {
        // constants (once per m): lane-parallel over h
        const int which = wid - 2;
        float acc = 0.f;
        #pragma unroll
        for (int hh = lane; hh < HID; hh += 32) {
            float a, b;
            if      (which == 0) { a = hb[hh];  b = sw0[hh]; }
            else if (which == 1) { a = hb[hh];  b = sw1[hh]; }
            else if (which == 2) { a = sw0[hh]; b = sw0[hh]; }
            else if (which == 3) { a = sw1[hh]; b = sw1[hh]; }
            else                 { a = sw0[hh]; b = sw1[hh]; }
            acc = fmaf(a, b, acc);
        }
        acc += __shfl_xor_sync(0xffffffffu, acc, 16);
        acc += __shfl_xor_sync(0xffffffffu, acc, 8);
        acc += __shfl_xor_sync(0xffffffffu, acc, 4);
        acc += __shfl_xor_sync(0xffffffffu, acc, 2);
        acc += __shfl_xor_sync(0xffffffffu, acc, 1);
        if (lane == 0) {
            __shared__ float cst[5];
            cst[which] = acc;
            __threadfence_block();
            // combined later by which==4? simpler: write partial targets directly
            if (which == 4) g_cstT[2][m] = -acc;
        }
    }
    __syncthreads();

    // finish constants (q==0): needs cst[0..3]; recompute cheaply in one warp
    if (q == 0 && tid == 0) {
        // serial but tiny relative to block: fold via su? Not available; do 4 dots of 256
        // NOTE: replaced below by direct computation to avoid smem plumbing
    }

    // nibble build: tid<64 -> (pos_local, nib)
    if (tid < 64) {
        const int pl = tid >> 4, nib = tid & 15;
        float a0 = 0.f, a1 = 0.f;
        #pragma unroll
        for (int b = 0; b < 4; ++b)
            if ((nib >> b) & 1) { const float2 u = su[pl * 4 + b]; a0 += u.x; a1 += u.y; }
        g_nib[q * 4 + pl][nib][m] = make_float2(a0, a1);
    }

    // constants c0..c3 -> g_cstT[0..1] (q==0): warp 7, lane-parallel pairs
    if (q == 0 && wid == 7) {
        // acc0 = Σhb·w0, acc2 = Σw0² (lanes 0..15 handle w0 side), w1 side lanes 16..31
        const float* sw = (lane < 16) ? sw0 : sw1;
        const int l2 = lane & 15;
        float ab = 0.f, qq = 0.f;
        #pragma unroll
        for (int hh = l2; hh < HID; hh += 16) {
            const float wv = sw[hh];
            ab = fmaf(hb[hh], wv, ab);
            qq = fmaf(wv, wv, qq);
        }
        #pragma unroll
        for (int s = 8; s >= 1; s >>= 1) {
            ab += __shfl_down_sync(0xffffffffu, ab, s);
            qq += __shfl_down_sync(0xffffffffu, qq, s);
        }
        if (l2 == 0) g_cstT[(lane >> 4)][m] = -ab - 0.5f * qq;
    }
}

// exp(L) for |L| <= 0.05, rel err < 5e-8
__device__ __forceinline__ float expq(float L) {
    return fmaf(L, fmaf(L, fmaf(L, 0.16666667f, 0.5f), 1.0f), 1.0f);
}

// 4 warps/block, TB=4 batch elements per warp; lane = step m.
// Register-batched nibble lookups (MLP=16 per batch), no smem, no sync.
__global__ __launch_bounds__(128, 4)
void rbm_main_kernel(const int* __restrict__ x, float* __restrict__ out)
{
    const int tid  = threadIdx.x;
    const int lane = tid & 31, wid = tid >> 5;
    const int m    = lane;
    const int k    = 2 * m;

    const int b0 = (blockIdx.x * 4 + wid) * TB;
    unsigned lo[TB], hi[TB];
    #pragma unroll
    for (int t = 0; t < TB; ++t) {
        const int v0 = x[(size_t)(b0 + t) * SORB + lane];
        const int v1 = x[(size_t)(b0 + t) * SORB + 32 + lane];
        lo[t] = __ballot_sync(0xffffffffu, v0 > 0);
        hi[t] = __ballot_sync(0xffffffffu, v1 > 0);
    }

    float L1[TB], L2[TB];
    #pragma unroll
    for (int t = 0; t < TB; ++t) {
        L1[t] = __ldg(&g_cstT[0][m]);
        L2[t] = __ldg(&g_cstT[1][m]);
    }

    const char* base = (const char*)g_nib + (size_t)lane * sizeof(float2);

    // 16 positions; 4 batches of (4 pos × TB) = 16 in-flight LDG.64 each
    #pragma unroll
    for (int b4 = 0; b4 < 4; ++b4) {
        float2 v[4 * TB];
        #pragma unroll
        for (int i = 0; i < 4; ++i) {
            const int p  = b4 * 4 + i;
            const int sh = (p & 7) * 4;
            #pragma unroll
            for (int t = 0; t < TB; ++t) {
                const unsigned w   = (p < 8) ? lo[t] : hi[t];
                const unsigned off = (sh < 8) ? ((w << (8 - sh)) & 0xF00u)
                                              : ((w >> (sh - 8)) & 0xF00u);
                v[i * TB + t] = __ldg((const float2*)(base + (size_t)p * 4096 + off));
            }
        }
        #pragma unroll
        for (int i = 0; i < 4; ++i)
            #pragma unroll
            for (int t = 0; t < TB; ++t) {
                L1[t] += v[i * TB + t].x;
                L2[t] += v[i * TB + t].y;
            }
    }

    const unsigned mlo = (k >= 32) ? 0xffffffffu : ((1u << k) - 1u);
    const unsigned mhi = (k > 32) ? ((1u << (k - 32)) - 1u) : 0u;
    const float negQ01 = __ldg(&g_cstT[2][m]);

    float terms[TB];
    #pragma unroll
    for (int t = 0; t < TB; ++t) {
        const float L3 = L1[t] + L2[t] + negQ01;
        float v0f = 1.f, v1f = expq(L1[t]), v2f = expq(L2[t]), v3f = expq(L3);

        const int nu = __popc(lo[t] & 0x55555555u & mlo) + __popc(hi[t] & 0x55555555u & mhi);
        const int nd = __popc(lo[t] & 0xAAAAAAAAu & mlo) + __popc(hi[t] & 0xAAAAAAAAu & mhi);

        if (m >= 8) {
            const int lower = m - 16;
            const bool ou = nu < 16, uu = nu > lower;
            const bool od = nd < 16, ud = nd > lower;
            v0f = (uu && ud) ? v0f : 0.f;
            v1f = (ou && ud) ? v1f : 0.f;
            v2f = (uu && od) ? v2f : 0.f;
            v3f = (ou && od) ? v3f : 0.f;
        }

        const float n2 = v0f*v0f + v1f*v1f + v2f*v2f + v3f*v3f;
        float inv = rsqrtf(fmaxf(n2, 1e-24f));
        inv = inv * fmaf(-0.5f * n2 * inv, inv, 1.5f);

        const int bu = (k < 32) ? ((lo[t] >> k) & 1)       : ((hi[t] >> (k - 32)) & 1);
        const int bd = (k < 32) ? ((lo[t] >> (k + 1)) & 1) : ((hi[t] >> (k - 31)) & 1);
        const int st = bu + 2 * bd;
        const float vs = st == 0 ? v0f : st == 1 ? v1f : st == 2 ? v2f : v3f;

        float term = vs * inv;
        term *= __shfl_xor_sync(0xffffffffu, term, 16);
        term *= __shfl_xor_sync(0xffffffffu, term, 8);
        term *= __shfl_xor_sync(0xffffffffu, term, 4);
        term *= __shfl_xor_sync(0xffffffffu, term, 2);
        term *= __shfl_xor_sync(0xffffffffu, term, 1);
        terms[t] = term;
    }

    float o = terms[0];
    #pragma unroll
    for (int t = 1; t < TB; ++t) o = (lane == t) ? terms[t] : o;
    if (lane < TB) out[b0 + lane] = o;
}

extern "C" void kernel_launch(void* const* d_in, const int* in_sizes, int n_in,
                              void* d_out, int out_size)
{
    const int*   x   = (const int*)d_in[0];
    const float* W   = (const float*)d_in[1];
    const float* hb  = (const float*)d_in[2];
    float*       out = (float*)d_out;

    precompute_kernel<<<NSTEP * 4, 256>>>(W, hb);
    rbm_main_kernel<<<BATCH / (4 * TB), 128>>>(x, out);
}

// round 12
// speedup vs baseline: 1.6012x; 1.2648x over previous
#include <cuda_runtime.h>
#include <cstdint>

#define SORB  64
#define HID   256
#define BATCH 8192
#define LEN   1056
#define NSTEP 32
#define TB    2      // batch elements per warp

// Byte subset-sum table (negated, zero for j >= 2m):
//   g_byte[p][byte][m] = -Σ_{b set in byte} Σ_h W[h,start(m)+8p+b]·(w0,w1)^m
// g_cstT[0][m] = -Σhb·w0 - 0.5Σw0² ; [1]: w1 version ; [2] = -Σw0·w1
__device__ float2 g_byte[8][256][32];
__device__ float  g_cstT[4][32];

// grid 256 = (m = bid>>3, p = bid&7); 256 threads.
__global__ __launch_bounds__(256)
void precompute_kernel(const float* __restrict__ W, const float* __restrict__ hb)
{
    const int m = blockIdx.x >> 3, p = blockIdx.x & 7;
    const int k = 2 * m, start = m * (m + 1);
    __shared__ float  sw0[HID], sw1[HID];
    __shared__ float  pp0[8][32], pp1[8][32];
    __shared__ float2 su[8];
    const int tid = threadIdx.x;
    const int lane = tid & 31, wid = tid >> 5;

    // stage w0,w1 (strided gather)
    {
        const float* pw = W + (size_t)tid * LEN + start + k;
        sw0[tid] = pw[0];
        sw1[tid] = pw[1];
    }
    __syncthreads();

    // u[j] for j in [8p, 8p+8): thread = (jl = tid&7, grp = tid>>3), 8 h each
    {
        const int jl = tid & 7, grp = tid >> 3;
        const int j = 8 * p + jl;
        float a0 = 0.f, a1 = 0.f;
        if (j < k) {
            const float* pw = W + start + j;
            #pragma unroll
            for (int hh = 0; hh < 8; ++hh) {
                const int h = grp * 8 + hh;
                const float wv = pw[(size_t)h * LEN];
                a0 = fmaf(wv, sw0[h], a0);
                a1 = fmaf(wv, sw1[h], a1);
            }
        }
        pp0[jl][grp] = a0;
        pp1[jl][grp] = a1;
    }
    __syncthreads();

    if (tid < 8) {
        float s0 = 0.f, s1 = 0.f;
        #pragma unroll
        for (int g = 0; g < 32; ++g) { s0 += pp0[tid][g]; s1 += pp1[tid][g]; }
        su[tid] = make_float2(-s0, -s1);
    }
    // constants (once per m, in p==0 blocks)
    if (p == 0 && wid == 2) {                 // -Σ w0·w1
        float acc = 0.f;
        #pragma unroll
        for (int hh = lane; hh < HID; hh += 32)
            acc = fmaf(sw0[hh], sw1[hh], acc);
        acc += __shfl_xor_sync(0xffffffffu, acc, 16);
        acc += __shfl_xor_sync(0xffffffffu, acc, 8);
        acc += __shfl_xor_sync(0xffffffffu, acc, 4);
        acc += __shfl_xor_sync(0xffffffffu, acc, 2);
        acc += __shfl_xor_sync(0xffffffffu, acc, 1);
        if (lane == 0) g_cstT[2][m] = -acc;
    }
    if (p == 0 && wid == 7) {                 // L1/L2 bases
        const float* sw = (lane < 16) ? sw0 : sw1;
        const int l2 = lane & 15;
        float ab = 0.f, qq = 0.f;
        #pragma unroll
        for (int hh = l2; hh < HID; hh += 16) {
            const float wv = sw[hh];
            ab = fmaf(hb[hh], wv, ab);
            qq = fmaf(wv, wv, qq);
        }
        #pragma unroll
        for (int s = 8; s >= 1; s >>= 1) {
            ab += __shfl_down_sync(0xffffffffu, ab, s);
            qq += __shfl_down_sync(0xffffffffu, qq, s);
        }
        if (l2 == 0) g_cstT[(lane >> 4)][m] = -ab - 0.5f * qq;
    }
    __syncthreads();

    // byte subset sums: tid = byte value
    {
        float a0 = 0.f, a1 = 0.f;
        #pragma unroll
        for (int b = 0; b < 8; ++b)
            if ((tid >> b) & 1) { const float2 u = su[b]; a0 += u.x; a1 += u.y; }
        g_byte[p][tid][m] = make_float2(a0, a1);
    }
}

// exp(L) for |L| <= 0.05, rel err < 5e-8
__device__ __forceinline__ float expq(float L) {
    return fmaf(L, fmaf(L, fmaf(L, 0.16666667f, 0.5f), 1.0f), 1.0f);
}

// 4 warps/block, TB=2 batch elements per warp; lane = step m.
// 16 byte-LUT loads total per warp, single MLP batch. No smem, no sync.
__global__ __launch_bounds__(128)
void rbm_main_kernel(const int* __restrict__ x, float* __restrict__ out)
{
    const int tid  = threadIdx.x;
    const int lane = tid & 31, wid = tid >> 5;
    const int m    = lane;
    const int k    = 2 * m;

    const int b0 = (blockIdx.x * 4 + wid) * TB;
    unsigned lo[TB], hi[TB];
    #pragma unroll
    for (int t = 0; t < TB; ++t) {
        const int v0 = x[(size_t)(b0 + t) * SORB + lane];
        const int v1 = x[(size_t)(b0 + t) * SORB + 32 + lane];
        lo[t] = __ballot_sync(0xffffffffu, v0 > 0);
        hi[t] = __ballot_sync(0xffffffffu, v1 > 0);
    }

    // Per-lane base into the byte table: entry addr = p*65536 + byte*256 + lane*8
    const char* base = (const char*)g_byte + (size_t)lane * sizeof(float2);

    // All 16 loads issued as one independent batch (MLP = 16)
    float2 v[8 * TB];
    #pragma unroll
    for (int p = 0; p < 8; ++p) {
        const int sh = p & 3;
        #pragma unroll
        for (int t = 0; t < TB; ++t) {
            const unsigned w   = (p < 4) ? lo[t] : hi[t];
            const unsigned off = (sh == 0) ? ((w << 8) & 0xFF00u)
                                           : ((w >> (8 * sh - 8)) & 0xFF00u);
            v[p * TB + t] = __ldg((const float2*)(base + (size_t)p * 65536 + off));
        }
    }

    float L1[TB], L2[TB];
    #pragma unroll
    for (int t = 0; t < TB; ++t) {
        L1[t] = __ldg(&g_cstT[0][m]);
        L2[t] = __ldg(&g_cstT[1][m]);
        #pragma unroll
        for (int p = 0; p < 8; ++p) {
            L1[t] += v[p * TB + t].x;
            L2[t] += v[p * TB + t].y;
        }
    }

    const unsigned mlo = (k >= 32) ? 0xffffffffu : ((1u << k) - 1u);
    const unsigned mhi = (k > 32) ? ((1u << (k - 32)) - 1u) : 0u;
    const float negQ01 = __ldg(&g_cstT[2][m]);

    float terms[TB];
    #pragma unroll
    for (int t = 0; t < TB; ++t) {
        const float L3 = L1[t] + L2[t] + negQ01;
        float v0f = 1.f, v1f = expq(L1[t]), v2f = expq(L2[t]), v3f = expq(L3);

        const int nu = __popc(lo[t] & 0x55555555u & mlo) + __popc(hi[t] & 0x55555555u & mhi);
        const int nd = __popc(lo[t] & 0xAAAAAAAAu & mlo) + __popc(hi[t] & 0xAAAAAAAAu & mhi);

        if (m >= 8) {                        // SYMMETRY && alpha_e <= k
            const int lower = m - 16;        // base + k/2
            const bool ou = nu < 16, uu = nu > lower;
            const bool od = nd < 16, ud = nd > lower;
            v0f = (uu && ud) ? v0f : 0.f;
            v1f = (ou && ud) ? v1f : 0.f;
            v2f = (uu && od) ? v2f : 0.f;
            v3f = (ou && od) ? v3f : 0.f;
        }

        const float n2 = v0f*v0f + v1f*v1f + v2f*v2f + v3f*v3f;
        float inv = rsqrtf(fmaxf(n2, 1e-24f));
        inv = inv * fmaf(-0.5f * n2 * inv, inv, 1.5f);   // Newton

        const int bu = (k < 32) ? ((lo[t] >> k) & 1)       : ((hi[t] >> (k - 32)) & 1);
        const int bd = (k < 32) ? ((lo[t] >> (k + 1)) & 1) : ((hi[t] >> (k - 31)) & 1);
        const int st = bu + 2 * bd;
        const float vs = st == 0 ? v0f : st == 1 ? v1f : st == 2 ? v2f : v3f;

        float term = vs * inv;
        term *= __shfl_xor_sync(0xffffffffu, term, 16);
        term *= __shfl_xor_sync(0xffffffffu, term, 8);
        term *= __shfl_xor_sync(0xffffffffu, term, 4);
        term *= __shfl_xor_sync(0xffffffffu, term, 2);
        term *= __shfl_xor_sync(0xffffffffu, term, 1);
        terms[t] = term;
    }

    float o = terms[0];
    #pragma unroll
    for (int t = 1; t < TB; ++t) o = (lane == t) ? terms[t] : o;
    if (lane < TB) out[b0 + lane] = o;
}

extern "C" void kernel_launch(void* const* d_in, const int* in_sizes, int n_in,
                              void* d_out, int out_size)
{
    const int*   x   = (const int*)d_in[0];
    const float* W   = (const float*)d_in[1];
    const float* hb  = (const float*)d_in[2];
    float*       out = (float*)d_out;

    precompute_kernel<<<NSTEP * 8, 256>>>(W, hb);
    rbm_main_kernel<<<BATCH / (4 * TB), 128>>>(x, out);
}